// round 9
// baseline (speedup 1.0000x reference)
#include <cuda_runtime.h>
#include <cuda_bf16.h>
#include <cstdint>

#define NSEQ   384
#define CDIM   128
#define NROWS  (NSEQ*NSEQ)          /* 147456 */
#define LN_EPS 1e-5f

/* ------------------------------------------------------------------ */
/* Scratch (device globals)                                            */
/* ------------------------------------------------------------------ */
__device__ float g_x [(size_t)NROWS*CDIM];   /* LN(z), tf32-rounded         */
__device__ __nv_bfloat16 g_ath[(size_t)CDIM*NROWS]; /* a hi, [c][i*N+k]     */
__device__ __nv_bfloat16 g_atl[(size_t)CDIM*NROWS]; /* a lo                 */
__device__ __nv_bfloat16 g_bth[(size_t)CDIM*NROWS]; /* b hi, [c][j*N+k]     */
__device__ __nv_bfloat16 g_btl[(size_t)CDIM*NROWS]; /* b lo                 */
__device__ float g_gs[(size_t)NROWS*CDIM];   /* sigmoid gate, [r][c], f32   */
__device__ float g_tt[(size_t)CDIM*NROWS];   /* t, [c][i*N+j], f32          */
__device__ float g_y [(size_t)NROWS*CDIM];   /* LN_out(t), tf32-rounded     */
__device__ float g_wcat[640*CDIM];           /* weights [n][k], tf32        */
__device__ float g_wot[CDIM*CDIM];           /* w_o^T [n][k], tf32          */
__device__ float g_bcat[640];

__device__ __forceinline__ float sigm(float x){ return 1.f/(1.f+__expf(-x)); }
__device__ __forceinline__ float f2tf(float f){
    unsigned u; asm("cvt.rna.tf32.f32 %0, %1;" : "=r"(u) : "f"(f));
    return __uint_as_float(u);
}
__device__ __forceinline__ uint32_t smem_u32(const void* p){
    uint32_t a;
    asm("{ .reg .u64 t; cvta.to.shared.u64 t, %1; cvt.u32.u64 %0, t; }"
        : "=r"(a) : "l"(p));
    return a;
}

#define MMA_TF32(d,a,b) asm volatile( \
    "mma.sync.aligned.m16n8k8.row.col.f32.tf32.tf32.f32 " \
    "{%0,%1,%2,%3},{%4,%5,%6,%7},{%8,%9},{%0,%1,%2,%3};" \
    : "+f"(d[0]),"+f"(d[1]),"+f"(d[2]),"+f"(d[3]) \
    : "r"(a[0]),"r"(a[1]),"r"(a[2]),"r"(a[3]),"r"(b[0]),"r"(b[1]))

#define MMA_BF16(d,a,b) asm volatile( \
    "mma.sync.aligned.m16n8k16.row.col.f32.bf16.bf16.f32 " \
    "{%0,%1,%2,%3},{%4,%5,%6,%7},{%8,%9},{%0,%1,%2,%3};" \
    : "+f"(d[0]),"+f"(d[1]),"+f"(d[2]),"+f"(d[3]) \
    : "r"(a[0]),"r"(a[1]),"r"(a[2]),"r"(a[3]),"r"(b[0]),"r"(b[1]))

#define LDSM4(r0,r1,r2,r3,a) asm volatile( \
    "ldmatrix.sync.aligned.m8n8.x4.shared.b16 {%0,%1,%2,%3}, [%4];" \
    : "=r"(r0),"=r"(r1),"=r"(r2),"=r"(r3) : "r"(a))

#define CP16(dst,src) asm volatile( \
    "cp.async.cg.shared.global [%0], [%1], 16;" :: "r"(dst), "l"(src))
#define CP_COMMIT() asm volatile("cp.async.commit_group;" ::: "memory")
#define CP_WAIT1()  asm volatile("cp.async.wait_group 1;" ::: "memory")
#define CP_WAIT0()  asm volatile("cp.async.wait_group 0;" ::: "memory")

/* ===================== tf32 path (gemm1 / gemm3) =================== */
#define PADK 20
#define STG_B   10240
#define STAGE_B 20480
#define NST     3
#define SMEM_MM (NST*STAGE_B)        /* 61440 bytes */

__device__ __forceinline__ void issue_chunk(uint32_t sbase, int stage,
                                            const float* __restrict__ A, int lda,
                                            const float* __restrict__ B, int ldb,
                                            int k0, int crow, int cseg)
{
    #pragma unroll
    for (int it=0; it<4; it++){
        int row = crow + it*32;
        uint32_t d = sbase + stage*STAGE_B + (row*PADK + cseg*4)*4;
        CP16(d,         A + (size_t)row*lda + k0 + cseg*4);
        CP16(d + STG_B, B + (size_t)row*ldb + k0 + cseg*4);
    }
    CP_COMMIT();
}

template<int KTOT>
__device__ __forceinline__ void mm_loop(const float* __restrict__ A, int lda,
                                        const float* __restrict__ B, int ldb,
                                        uint32_t sbase,
                                        float (&acc)[4][8][4])
{
    const int tid  = threadIdx.x;
    const int warp = tid>>5, lane = tid&31;
    const int wm = warp>>1, wn = warp&1;
    constexpr int NC = KTOT/16;

    const int crow = tid>>2, cseg = tid&3;
    const int ar  = lane & 15,          ac4 = (lane>>4)*4;
    const int br  = (lane&7)+((lane>>4)<<3), bc4 = ((lane>>3)&1)*4;

    issue_chunk(sbase, 0, A, lda, B, ldb, 0,  crow, cseg);
    issue_chunk(sbase, 1, A, lda, B, ldb, 16, crow, cseg);

    int st = 0;
    for (int c=0; c<NC; c++){
        if (c < NC-1) CP_WAIT1(); else CP_WAIT0();
        __syncthreads();

        if (c+2 < NC){
            int nst = st+2; if (nst >= NST) nst -= NST;
            issue_chunk(sbase, nst, A, lda, B, ldb, (c+2)*16, crow, cseg);
        }

        const uint32_t sA = sbase + st*STAGE_B;
        const uint32_t sB = sA + STG_B;
        #pragma unroll
        for (int kk=0; kk<2; kk++){
            unsigned af[4][4], bf[4][4];
            #pragma unroll
            for (int mi=0; mi<4; mi++){
                uint32_t a = sA + ((wm*64 + mi*16 + ar)*PADK + kk*8 + ac4)*4;
                LDSM4(af[mi][0], af[mi][1], af[mi][2], af[mi][3], a);
            }
            #pragma unroll
            for (int p=0; p<4; p++){
                uint32_t a = sB + ((wn*64 + p*16 + br)*PADK + kk*8 + bc4)*4;
                LDSM4(bf[p][0], bf[p][1], bf[p][2], bf[p][3], a);
            }
            #pragma unroll
            for (int mi=0; mi<4; mi++)
                #pragma unroll
                for (int p=0; p<4; p++){
                    unsigned b0[2] = { bf[p][0], bf[p][1] };
                    unsigned b1[2] = { bf[p][2], bf[p][3] };
                    MMA_TF32(acc[mi][2*p  ], af[mi], b0);
                    MMA_TF32(acc[mi][2*p+1], af[mi], b1);
                }
        }
        if (++st >= NST) st -= NST;
    }
}

#define ACC_ZERO8(acc) do { \
    _Pragma("unroll") \
    for (int _i=0;_i<4;_i++) \
        _Pragma("unroll") \
        for (int _j=0;_j<8;_j++) \
            _Pragma("unroll") \
            for (int _r=0;_r<4;_r++) acc[_i][_j][_r]=0.f; \
} while(0)

/* ===================== bf16 split path (gemm2) ===================== */
#define PADB  48                     /* bytes per 16-elt bf16 row (16B-aligned, LDSM conflict-free) */
#define TILE2_B  (128*PADB)          /* 6144 B per tile */
#define STAGE2_B (4*TILE2_B)         /* Ah,Al,Bh,Bl = 24576 B */
#define NST2     3
#define SMEM_MM2 (NST2*STAGE2_B)     /* 73728 B */

__device__ __forceinline__ void issue_chunk2(uint32_t sbase, int stage,
                                             const __nv_bfloat16* __restrict__ Ah,
                                             const __nv_bfloat16* __restrict__ Al,
                                             const __nv_bfloat16* __restrict__ Bh,
                                             const __nv_bfloat16* __restrict__ Bl,
                                             int k0, int crow, int cseg)
{
    size_t off = (size_t)crow*NSEQ + k0 + cseg*8;
    uint32_t d = sbase + stage*STAGE2_B + crow*PADB + cseg*16;
    CP16(d,             Ah + off);
    CP16(d +   TILE2_B, Al + off);
    CP16(d + 2*TILE2_B, Bh + off);
    CP16(d + 3*TILE2_B, Bl + off);
    CP_COMMIT();
}

/* ------------------------------------------------------------------ */
/* K0: transposed tf32 weight concat [n][k] + biases + w_o^T           */
/* ------------------------------------------------------------------ */
__global__ void k_build(const float* __restrict__ wap, const float* __restrict__ wag,
                        const float* __restrict__ wbp, const float* __restrict__ wbg,
                        const float* __restrict__ wg,  const float* __restrict__ wo,
                        const float* __restrict__ bap, const float* __restrict__ bag,
                        const float* __restrict__ bbp, const float* __restrict__ bbg,
                        const float* __restrict__ bg)
{
    int id = blockIdx.x*blockDim.x + threadIdx.x;
    if (id < CDIM*640){
        int k = id/640, col = id%640;
        float v;
        if (col < 256)      { int t = col>>1;        v = (col&1) ? wag[k*CDIM+t] : wap[k*CDIM+t]; }
        else if (col < 512) { int t = (col-256)>>1;  v = (col&1) ? wbg[k*CDIM+t] : wbp[k*CDIM+t]; }
        else                {                        v = wg[k*CDIM + (col-512)]; }
        g_wcat[col*CDIM + k] = f2tf(v);
        if (k == 0){
            float b;
            if (col < 256)      { int t = col>>1;       b = (col&1) ? bag[t] : bap[t]; }
            else if (col < 512) { int t = (col-256)>>1; b = (col&1) ? bbg[t] : bbp[t]; }
            else                {                       b = bg[col-512]; }
            g_bcat[col] = b;
        }
    } else {
        int id2 = id - CDIM*640;
        if (id2 < CDIM*CDIM){
            int n = id2 >> 7, k = id2 & 127;
            g_wot[n*CDIM + k] = f2tf(wo[k*CDIM + n]);
        }
    }
}

/* ------------------------------------------------------------------ */
/* K1: input LayerNorm, one warp per row, tf32-rounded store           */
/* ------------------------------------------------------------------ */
__global__ void k_ln_in(const float* __restrict__ z,
                        const float* __restrict__ w, const float* __restrict__ b)
{
    int warp = threadIdx.x>>5, lane = threadIdx.x&31;
    size_t row = (size_t)blockIdx.x*8 + warp;
    float4 v = ((const float4*)(z + row*CDIM))[lane];
    float s = v.x+v.y+v.z+v.w;
    #pragma unroll
    for (int o=16;o;o>>=1) s += __shfl_xor_sync(~0u, s, o);
    float mu = s*(1.f/128.f);
    float dx=v.x-mu, dy=v.y-mu, dz=v.z-mu, dw=v.w-mu;
    float q = dx*dx+dy*dy+dz*dz+dw*dw;
    #pragma unroll
    for (int o=16;o;o>>=1) q += __shfl_xor_sync(~0u, q, o);
    float rs = rsqrtf(q*(1.f/128.f) + LN_EPS);
    float4 wv = ((const float4*)w)[lane];
    float4 bv = ((const float4*)b)[lane];
    float4 o4;
    o4.x = f2tf(dx*rs*wv.x + bv.x);  o4.y = f2tf(dy*rs*wv.y + bv.y);
    o4.z = f2tf(dz*rs*wv.z + bv.z);  o4.w = f2tf(dw*rs*wv.w + bv.w);
    ((float4*)(g_x + row*CDIM))[lane] = o4;
}

/* ------------------------------------------------------------------ */
/* K2: projection GEMM + gated epilogue. grid (5, 1152), 128 threads   */
/* a/b staged through smem, split into (hi,lo) bf16 planes, 16B stores */
/* ------------------------------------------------------------------ */
__device__ __forceinline__ unsigned pk2(float a, float b){
    __nv_bfloat162 t = __floats2bfloat162_rn(a, b);
    return *(unsigned*)&t;
}

__global__ __launch_bounds__(128) void k_gemm1(const float* __restrict__ mask)
{
    extern __shared__ float dynsm[];
    const uint32_t sbase = smem_u32(dynsm);
    const int nb = blockIdx.x;
    const size_t m0 = (size_t)blockIdx.y*128;
    const int n0 = nb*128;

    float acc[4][8][4];
    ACC_ZERO8(acc);
    mm_loop<CDIM>(g_x + m0*CDIM, CDIM,
                  g_wcat + (size_t)n0*CDIM, CDIM, sbase, acc);

    const int tid = threadIdx.x;
    const int warp = tid>>5, lane = tid&31;
    const int wm = warp>>1, wn = warp&1;
    const int tr = lane>>2, tc = lane&3;

    if (nb < 4){
        __syncthreads();     /* reuse pipeline smem as [64][132] transpose buf */
        #pragma unroll
        for (int mi=0;mi<4;mi++){
            int rl = wm*64 + mi*16 + tr;
            size_t r1 = m0 + rl;
            float mk1 = mask[r1], mk2 = mask[r1+8];
            #pragma unroll
            for (int ni=0;ni<8;ni++){
                int gcol = n0 + wn*64 + ni*8 + 2*tc;
                int chl  = wn*32 + ni*4 + tc;
                float b0 = g_bcat[gcol], b1 = g_bcat[gcol+1];
                float c0 = acc[mi][ni][0]+b0, c1 = acc[mi][ni][1]+b1;
                float c2 = acc[mi][ni][2]+b0, c3 = acc[mi][ni][3]+b1;
                dynsm[chl*132 + rl    ] = mk1*sigm(c1)*c0;
                dynsm[chl*132 + rl + 8] = mk2*sigm(c3)*c2;
            }
        }
        __syncthreads();
        __nv_bfloat16* dh = (nb < 2) ? g_ath : g_bth;
        __nv_bfloat16* dl = (nb < 2) ? g_atl : g_btl;
        const int chb = (nb&1)*64;
        const int sub = tid&3;
        #pragma unroll
        for (int cc=0; cc<2; cc++){
            int ch = (tid>>2) + cc*32;
            const float* srow = dynsm + ch*132 + sub*32;
            size_t base = (size_t)(chb+ch)*NROWS + m0 + sub*32;
            #pragma unroll
            for (int i=0;i<4;i++){
                float4 f0 = *(const float4*)(srow + i*8);
                float4 f1 = *(const float4*)(srow + i*8 + 4);
                __nv_bfloat162 h0 = __floats2bfloat162_rn(f0.x, f0.y);
                __nv_bfloat162 h1 = __floats2bfloat162_rn(f0.z, f0.w);
                __nv_bfloat162 h2 = __floats2bfloat162_rn(f1.x, f1.y);
                __nv_bfloat162 h3 = __floats2bfloat162_rn(f1.z, f1.w);
                uint4 uh = make_uint4(*(unsigned*)&h0, *(unsigned*)&h1,
                                      *(unsigned*)&h2, *(unsigned*)&h3);
                uint4 ul = make_uint4(
                    pk2(f0.x-__low2float(h0), f0.y-__high2float(h0)),
                    pk2(f0.z-__low2float(h1), f0.w-__high2float(h1)),
                    pk2(f1.x-__low2float(h2), f1.y-__high2float(h2)),
                    pk2(f1.z-__low2float(h3), f1.w-__high2float(h3)));
                *(uint4*)(dh + base + i*8) = uh;
                *(uint4*)(dl + base + i*8) = ul;
            }
        }
    } else {
        #pragma unroll
        for (int mi=0;mi<4;mi++){
            size_t r1 = m0 + (size_t)(wm*64 + mi*16 + tr);
            size_t r2 = r1 + 8;
            #pragma unroll
            for (int ni=0;ni<8;ni++){
                int gcol = n0 + wn*64 + ni*8 + 2*tc;
                float b0 = g_bcat[gcol], b1 = g_bcat[gcol+1];
                int gc = gcol - 512;
                g_gs[r1*CDIM+gc  ]=sigm(acc[mi][ni][0]+b0);
                g_gs[r1*CDIM+gc+1]=sigm(acc[mi][ni][1]+b1);
                g_gs[r2*CDIM+gc  ]=sigm(acc[mi][ni][2]+b0);
                g_gs[r2*CDIM+gc+1]=sigm(acc[mi][ni][3]+b1);
            }
        }
    }
}

/* ------------------------------------------------------------------ */
/* K3: einsum T_c = A_c @ B_c^T, bf16 3-MMA split. grid (3,3,128),     */
/* 256 threads, 8 warps (2m x 4n), warp tile 64x32, 3-stage ring       */
/* ------------------------------------------------------------------ */
__global__ __launch_bounds__(256,2) void k_gemm2()
{
    extern __shared__ float dynsm[];
    const uint32_t sbase = smem_u32(dynsm);
    const size_t plane = (size_t)blockIdx.z*NROWS;
    const int m0 = blockIdx.y*128, n0 = blockIdx.x*128;

    const __nv_bfloat16* Ah = g_ath + plane + (size_t)m0*NSEQ;
    const __nv_bfloat16* Al = g_atl + plane + (size_t)m0*NSEQ;
    const __nv_bfloat16* Bh = g_bth + plane + (size_t)n0*NSEQ;
    const __nv_bfloat16* Bl = g_btl + plane + (size_t)n0*NSEQ;

    const int tid = threadIdx.x;
    const int warp = tid>>5, lane = tid&31;
    const int wm = warp>>2, wn = warp&3;
    const int crow = tid & 127, cseg = tid>>7;
    const int lrow = lane & 15, lhalf = lane>>4;
    constexpr int NC = NSEQ/16;      /* 24 */

    float acc[4][4][4];
    #pragma unroll
    for (int i=0;i<4;i++)
        #pragma unroll
        for (int j=0;j<4;j++)
            #pragma unroll
            for (int r=0;r<4;r++) acc[i][j][r]=0.f;

    issue_chunk2(sbase, 0, Ah, Al, Bh, Bl, 0,  crow, cseg);
    issue_chunk2(sbase, 1, Ah, Al, Bh, Bl, 16, crow, cseg);

    int st = 0;
    for (int c=0; c<NC; c++){
        if (c < NC-1) CP_WAIT1(); else CP_WAIT0();
        __syncthreads();

        if (c+2 < NC){
            int nst = st+2; if (nst >= NST2) nst -= NST2;
            issue_chunk2(sbase, nst, Ah, Al, Bh, Bl, (c+2)*16, crow, cseg);
        }

        const uint32_t sa = sbase + st*STAGE2_B;
        unsigned ah[4][4], al[4][4], bh[2][4], bl[2][4];
        #pragma unroll
        for (int mi=0; mi<4; mi++){
            uint32_t a = sa + (wm*64 + mi*16 + lrow)*PADB + lhalf*16;
            LDSM4(ah[mi][0], ah[mi][1], ah[mi][2], ah[mi][3], a);
            LDSM4(al[mi][0], al[mi][1], al[mi][2], al[mi][3], a + TILE2_B);
        }
        #pragma unroll
        for (int q=0; q<2; q++){
            uint32_t a = sa + 2*TILE2_B + (wn*32 + q*16 + lrow)*PADB + lhalf*16;
            LDSM4(bh[q][0], bh[q][1], bh[q][2], bh[q][3], a);
            LDSM4(bl[q][0], bl[q][1], bl[q][2], bl[q][3], a + TILE2_B);
        }
        #pragma unroll
        for (int mi=0; mi<4; mi++)
            #pragma unroll
            for (int q=0; q<2; q++)
                #pragma unroll
                for (int e=0; e<2; e++){
                    unsigned bhf[2] = { bh[q][e], bh[q][e+2] };
                    unsigned blf[2] = { bl[q][e], bl[q][e+2] };
                    MMA_BF16(acc[mi][q*2+e], ah[mi], bhf);
                    MMA_BF16(acc[mi][q*2+e], ah[mi], blf);
                    MMA_BF16(acc[mi][q*2+e], al[mi], bhf);
                }
        if (++st >= NST2) st -= NST2;
    }

    const int tr = lane>>2, tc = lane&3;
    #pragma unroll
    for (int mi=0;mi<4;mi++){
        size_t i1 = (size_t)(m0 + wm*64 + mi*16 + tr);
        size_t i2 = i1 + 8;
        #pragma unroll
        for (int ni=0;ni<4;ni++){
            int j = n0 + wn*32 + ni*8 + 2*tc;
            *(float2*)(g_tt + plane + i1*NSEQ + j) = make_float2(acc[mi][ni][0], acc[mi][ni][1]);
            *(float2*)(g_tt + plane + i2*NSEQ + j) = make_float2(acc[mi][ni][2], acc[mi][ni][3]);
        }
    }
}

/* ------------------------------------------------------------------ */
/* K4: gather t over channel planes + output LayerNorm (tf32 store)    */
/* ------------------------------------------------------------------ */
__global__ void k_gather(const float* __restrict__ lw, const float* __restrict__ lb)
{
    __shared__ float sh[128][33];
    const int tid = threadIdx.x;
    const size_t r0 = (size_t)blockIdx.x*32;
    #pragma unroll
    for (int it=0;it<16;it++){
        int idx = it*256 + tid;
        int c = idx>>5, r = idx&31;
        sh[c][r] = g_tt[(size_t)c*NROWS + r0 + r];
    }
    __syncthreads();
    const int warp = tid>>5, lane = tid&31;
    #pragma unroll
    for (int rr=0;rr<4;rr++){
        int r = warp*4 + rr;
        float v0=sh[lane][r], v1=sh[lane+32][r], v2=sh[lane+64][r], v3=sh[lane+96][r];
        float s = v0+v1+v2+v3;
        #pragma unroll
        for (int o=16;o;o>>=1) s += __shfl_xor_sync(~0u, s, o);
        float mu = s*(1.f/128.f);
        float d0=v0-mu,d1=v1-mu,d2=v2-mu,d3=v3-mu;
        float q = d0*d0+d1*d1+d2*d2+d3*d3;
        #pragma unroll
        for (int o=16;o;o>>=1) q += __shfl_xor_sync(~0u, q, o);
        float rs = rsqrtf(q*(1.f/128.f) + LN_EPS);
        float* yr = g_y + (r0+r)*CDIM;
        yr[lane   ] = f2tf(d0*rs*lw[lane   ] + lb[lane   ]);
        yr[lane+32] = f2tf(d1*rs*lw[lane+32] + lb[lane+32]);
        yr[lane+64] = f2tf(d2*rs*lw[lane+64] + lb[lane+64]);
        yr[lane+96] = f2tf(d3*rs*lw[lane+96] + lb[lane+96]);
    }
}

/* ------------------------------------------------------------------ */
/* K5: output GEMM * gate. grid (1152), 128 threads                    */
/* ------------------------------------------------------------------ */
__global__ __launch_bounds__(128) void k_gemm3(const float* __restrict__ bo,
                                               float* __restrict__ out)
{
    extern __shared__ float dynsm[];
    const uint32_t sbase = smem_u32(dynsm);
    const size_t m0 = (size_t)blockIdx.x*128;

    float acc[4][8][4];
    ACC_ZERO8(acc);
    mm_loop<CDIM>(g_y + m0*CDIM, CDIM, g_wot, CDIM, sbase, acc);

    const int warp = threadIdx.x>>5, lane = threadIdx.x&31;
    const int wm = warp>>1, wn = warp&1;
    const int tr = lane>>2, tc = lane&3;

    #pragma unroll
    for (int mi=0;mi<4;mi++){
        size_t r1 = m0 + (size_t)(wm*64 + mi*16 + tr);
        size_t r2 = r1 + 8;
        #pragma unroll
        for (int ni=0;ni<8;ni++){
            int gcol = wn*64 + ni*8 + 2*tc;
            float b0 = bo[gcol], b1 = bo[gcol+1];
            float2 gt1 = *(const float2*)(g_gs + r1*CDIM + gcol);
            float2 gt2 = *(const float2*)(g_gs + r2*CDIM + gcol);
            *(float2*)(out + r1*CDIM + gcol) =
                make_float2(gt1.x*(acc[mi][ni][0]+b0), gt1.y*(acc[mi][ni][1]+b1));
            *(float2*)(out + r2*CDIM + gcol) =
                make_float2(gt2.x*(acc[mi][ni][2]+b0), gt2.y*(acc[mi][ni][3]+b1));
        }
    }
}

/* ------------------------------------------------------------------ */
extern "C" void kernel_launch(void* const* d_in, const int* in_sizes, int n_in,
                              void* d_out, int out_size)
{
    const float* z    = (const float*)d_in[0];
    const float* mask = (const float*)d_in[1];
    const float* lniw = (const float*)d_in[2];
    const float* lnib = (const float*)d_in[3];
    const float* wap  = (const float*)d_in[4];
    const float* bap  = (const float*)d_in[5];
    const float* wag  = (const float*)d_in[6];
    const float* bag  = (const float*)d_in[7];
    const float* wbp  = (const float*)d_in[8];
    const float* bbp  = (const float*)d_in[9];
    const float* wbg  = (const float*)d_in[10];
    const float* bbg  = (const float*)d_in[11];
    const float* wg   = (const float*)d_in[12];
    const float* bg   = (const float*)d_in[13];
    const float* lnow = (const float*)d_in[14];
    const float* lnob = (const float*)d_in[15];
    const float* wo   = (const float*)d_in[16];
    const float* bo   = (const float*)d_in[17];
    float* out = (float*)d_out;

    cudaFuncSetAttribute(k_gemm1, cudaFuncAttributeMaxDynamicSharedMemorySize, SMEM_MM);
    cudaFuncSetAttribute(k_gemm2, cudaFuncAttributeMaxDynamicSharedMemorySize, SMEM_MM2);
    cudaFuncSetAttribute(k_gemm3, cudaFuncAttributeMaxDynamicSharedMemorySize, SMEM_MM);

    k_build<<<(CDIM*640 + CDIM*CDIM + 255)/256, 256>>>(wap,wag,wbp,wbg,wg,wo,
                                                       bap,bag,bbp,bbg,bg);
    k_ln_in<<<NROWS/8, 256>>>(z, lniw, lnib);
    dim3 g1(5, NROWS/128);
    k_gemm1<<<g1, 128, SMEM_MM>>>(mask);
    dim3 g2(NSEQ/128, NSEQ/128, CDIM);
    k_gemm2<<<g2, 256, SMEM_MM2>>>();
    k_gather<<<NROWS/32, 256>>>(lnow, lnob);
    k_gemm3<<<NROWS/128, 128, SMEM_MM>>>(bo, out);
}